// round 16
// baseline (speedup 1.0000x reference)
#include <cuda_runtime.h>
#include <cstdint>

// PolicyEncoder gather-sum:
// out[n, :] = bias + w_state0[obs0[n]] + w_state1[obs1[n]] + w_act0[act0[n]] + w_act1[act1[n]]
// N = 262144 rows, D = 128 floats per row.
//
// R16 = R14 gather pipeline (consume-then-issue, 40 warps/SM) + TMA bulk
// output stores:
//  - Blocks tile-stride over 32-row tiles (8192 tiles). Warp w owns rows
//    tb+4w..tb+4w+3 of each tile, keeping its 2-stage gather pipeline alive
//    across tile boundaries.
//  - Results go to a double-buffered 16KB smem tile; after __syncthreads one
//    thread issues cp.async.bulk (TMA) of the whole contiguous tile. Output
//    leaves the SM as large linear bursts on the TMA path instead of 5920
//    warps' interleaved 512B STG scatter -> better HBM read/write turnaround.
//  - Double buffer + bulk_group wait(1) overlaps TMA drain with next tile.

#define TILE_ROWS 32
#define RPW 4                        // rows per warp per tile (8 warps)

struct Idx { int i0, i1, i2, i3; };

__device__ __forceinline__ Idx load_idx(const int* __restrict__ o0,
                                        const int* __restrict__ o1,
                                        const int* __restrict__ a0,
                                        const int* __restrict__ a1, int r) {
    Idx x;
    x.i0 = __ldg(o0 + r);
    x.i1 = __ldg(o1 + r);
    x.i2 = __ldg(a0 + r);
    x.i3 = __ldg(a1 + r);
    return x;
}

__global__ void __launch_bounds__(256, 5)
policy_encoder_kernel(const int* __restrict__ obs0,
                      const int* __restrict__ obs1,
                      const int* __restrict__ act0,
                      const int* __restrict__ act1,
                      const float4* __restrict__ w0,   // [OBS0, 32] as float4
                      const float4* __restrict__ w1,
                      const float4* __restrict__ w2,
                      const float4* __restrict__ w3,
                      const float4* __restrict__ bias, // [32]
                      float4* __restrict__ out,        // [N, 32]
                      int n, int tilesTotal)
{
    extern __shared__ float4 sm[];     // [2][TILE_ROWS][32] float4 = 32KB

    const int tid  = threadIdx.x;
    const int lane = tid & 31;
    const int warp = tid >> 5;
    const int last = n - 1;
    const int tStride = gridDim.x;

    const float4 b = __ldg(bias + lane);

    int ti = blockIdx.x;
    if (ti >= tilesTotal) return;      // (never at these sizes; whole block)

    // ---- pipeline prologue: gathers for this warp's first row, indices for
    //      the row after it ----
    int r0 = ti * TILE_ROWS + warp * RPW;
    int r0c = r0 <= last ? r0 : last;
    Idx ic = load_idx(obs0, obs1, act0, act1, r0c);
    int rn = r0 + 1; rn = rn <= last ? rn : last;
    Idx in_ = load_idx(obs0, obs1, act0, act1, rn);

    float4 g0 = __ldg(w0 + (size_t)ic.i0 * 32 + lane);
    float4 g1 = __ldg(w1 + (size_t)ic.i1 * 32 + lane);
    float4 g2 = __ldg(w2 + (size_t)ic.i2 * 32 + lane);
    float4 g3 = __ldg(w3 + (size_t)ic.i3 * 32 + lane);

    int iter = 0;
    for (; ti < tilesTotal; ti += tStride, ++iter) {
        const int tb = ti * TILE_ROWS;
        const int nt = ti + tStride;           // this block's next tile
        const int p  = iter & 1;
        float4* buf = sm + (size_t)p * (TILE_ROWS * 32);

        // ensure the TMA store that used THIS buffer (2 iters ago) is done
        if (tid == 0)
            asm volatile("cp.async.bulk.wait_group 1;" ::: "memory");
        __syncthreads();

        #pragma unroll
        for (int k = 0; k < RPW; ++k) {
            const int r = tb + warp * RPW + k;

            // row two ahead in this warp's sequence
            int r2 = (k < RPW - 2) ? (r + 2)
                                   : (nt * TILE_ROWS + warp * RPW + (k - (RPW - 2)));
            r2 = r2 <= last ? r2 : last;
            Idx inn = load_idx(obs0, obs1, act0, act1, r2);

            // consume current row into the smem tile
            if (r <= last) {
                float4 res;
                res.x = b.x + g0.x + g1.x + g2.x + g3.x;
                res.y = b.y + g0.y + g1.y + g2.y + g3.y;
                res.z = b.z + g0.z + g1.z + g2.z + g3.z;
                res.w = b.w + g0.w + g1.w + g2.w + g3.w;
                buf[(warp * RPW + k) * 32 + lane] = res;
            }

            // issue gathers for the next row into the same registers
            g0 = __ldg(w0 + (size_t)in_.i0 * 32 + lane);
            g1 = __ldg(w1 + (size_t)in_.i1 * 32 + lane);
            g2 = __ldg(w2 + (size_t)in_.i2 * 32 + lane);
            g3 = __ldg(w3 + (size_t)in_.i3 * 32 + lane);
            in_ = inn;
        }

        __syncthreads();

        if (tid == 0) {
            int rows = n - tb; if (rows > TILE_ROWS) rows = TILE_ROWS;
            uint32_t sAddr;
            asm("{ .reg .u64 t; cvta.to.shared.u64 t, %1; cvt.u32.u64 %0, t; }"
                : "=r"(sAddr) : "l"(buf));
            if (rows > 0) {
                asm volatile("fence.proxy.async;" ::: "memory");
                const char* dst = (const char*)(out + (size_t)tb * 32);
                asm volatile(
                    "cp.async.bulk.global.shared::cta.bulk_group [%0], [%1], %2;"
                    :: "l"(dst), "r"(sAddr), "r"(rows * 512) : "memory");
            }
            asm volatile("cp.async.bulk.commit_group;" ::: "memory");
        }
    }

    if (tid == 0)
        asm volatile("cp.async.bulk.wait_group 0;" ::: "memory");
}

extern "C" void kernel_launch(void* const* d_in, const int* in_sizes, int n_in,
                              void* d_out, int out_size)
{
    const int*    obs0 = (const int*)d_in[0];
    const int*    obs1 = (const int*)d_in[1];
    const int*    act0 = (const int*)d_in[2];
    const int*    act1 = (const int*)d_in[3];
    const float4* w0   = (const float4*)d_in[4];
    const float4* w1   = (const float4*)d_in[5];
    const float4* w2   = (const float4*)d_in[6];
    const float4* w3   = (const float4*)d_in[7];
    const float4* bias = (const float4*)d_in[8];
    float4*       out  = (float4*)d_out;

    const int n = in_sizes[0];                       // number of rows (N)
    const int tilesTotal = (n + TILE_ROWS - 1) / TILE_ROWS;

    const int threads = 256;                          // 8 warps/block
    const int blocks  = 148 * 5;                      // one exact wave, 5/SM
    const int smemBytes = 2 * TILE_ROWS * 32 * sizeof(float4);   // 32KB

    policy_encoder_kernel<<<blocks, threads, smemBytes>>>(
        obs0, obs1, act0, act1, w0, w1, w2, w3, bias, out, n, tilesTotal);
}

// round 17
// speedup vs baseline: 1.2826x; 1.2826x over previous
#include <cuda_runtime.h>
#include <cstdint>

// PolicyEncoder gather-sum:
// out[n, :] = bias + w_state0[obs0[n]] + w_state1[obs1[n]] + w_act0[act0[n]] + w_act1[act1[n]]
// N = 262144 rows, D = 128 floats per row.
//
// R17 = R14 with act gathers UN-pipelined:
//  - State-table gathers (DRAM/L2-miss latency) stay 1 iteration ahead in the
//    consume-then-issue pipeline.
//  - Act-table gathers (L1/L2 hits, short latency) are issued and consumed in
//    the same iteration -> 8 fewer payload registers carried.
//  - Single-step index prefetch (in_ = indices of NEXT row) instead of
//    2-step, freeing 4 more regs.
//  - Target <=42 regs -> __launch_bounds__(256, 6) -> 48 warps/SM, the one
//    occupancy point above R14 (40 warps) not yet measured.

__global__ void __launch_bounds__(256, 6)
policy_encoder_kernel(const int* __restrict__ obs0,
                      const int* __restrict__ obs1,
                      const int* __restrict__ act0,
                      const int* __restrict__ act1,
                      const float4* __restrict__ w0,   // [OBS0, 32] state
                      const float4* __restrict__ w1,   // [OBS1, 32] state
                      const float4* __restrict__ w2,   // [ACT0, 32] act
                      const float4* __restrict__ w3,   // [ACT1, 32] act
                      const float4* __restrict__ bias, // [32]
                      float4* __restrict__ out,        // [N, 32]
                      int n)
{
    const int lane   = threadIdx.x & 31;
    const int gw     = (int)((blockIdx.x * blockDim.x + threadIdx.x) >> 5);
    const int stride = (int)((gridDim.x * blockDim.x) >> 5);

    if (gw >= n) return;

    const float4 b = __ldg(bias + lane);
    const int last = n - 1;

    // ---- prologue ----
    // current row's act indices + state gathers in flight.
    int a2 = __ldg(act0 + gw);
    int a3 = __ldg(act1 + gw);
    float4 g0, g1;
    {
        const int i0 = __ldg(obs0 + gw);
        const int i1 = __ldg(obs1 + gw);
        g0 = __ldg(w0 + (size_t)i0 * 32 + lane);
        g1 = __ldg(w1 + (size_t)i1 * 32 + lane);
    }

    // ---- steady state ----
    for (int r = gw; r <= last; r += stride) {
        // next row's indices (broadcast loads, L1/L2-hot)
        int rn = r + stride; rn = rn <= last ? rn : last;
        const int j0 = __ldg(obs0 + rn);
        const int j1 = __ldg(obs1 + rn);
        const int j2 = __ldg(act0 + rn);
        const int j3 = __ldg(act1 + rn);

        // act gathers for the CURRENT row (short-latency cache hits)
        const float4 h2 = __ldg(w2 + (size_t)a2 * 32 + lane);
        const float4 h3 = __ldg(w3 + (size_t)a3 * 32 + lane);

        // consume row r: state gathers issued one iteration ago + act now
        float4 res;
        res.x = b.x + g0.x + g1.x + h2.x + h3.x;
        res.y = b.y + g0.y + g1.y + h2.y + h3.y;
        res.z = b.z + g0.z + g1.z + h2.z + h3.z;
        res.w = b.w + g0.w + g1.w + h2.w + h3.w;
        __stcs(out + (size_t)r * 32 + lane, res);

        // issue next row's state gathers into the same registers
        g0 = __ldg(w0 + (size_t)j0 * 32 + lane);
        g1 = __ldg(w1 + (size_t)j1 * 32 + lane);
        a2 = j2; a3 = j3;
    }
}

extern "C" void kernel_launch(void* const* d_in, const int* in_sizes, int n_in,
                              void* d_out, int out_size)
{
    const int*    obs0 = (const int*)d_in[0];
    const int*    obs1 = (const int*)d_in[1];
    const int*    act0 = (const int*)d_in[2];
    const int*    act1 = (const int*)d_in[3];
    const float4* w0   = (const float4*)d_in[4];
    const float4* w1   = (const float4*)d_in[5];
    const float4* w2   = (const float4*)d_in[6];
    const float4* w3   = (const float4*)d_in[7];
    const float4* bias = (const float4*)d_in[8];
    float4*       out  = (float4*)d_out;

    const int n = in_sizes[0];     // number of rows (N)
    const int threads = 256;       // 8 warps/block
    const int blocks  = 148 * 6;   // one exact wave at 6 blocks/SM

    policy_encoder_kernel<<<blocks, threads>>>(obs0, obs1, act0, act1,
                                               w0, w1, w2, w3, bias, out, n);
}